// round 1
// baseline (speedup 1.0000x reference)
#include <cuda_runtime.h>
#include <math.h>
#include <stdint.h>

#define NB 16
#define NN 2048
#define NTOT (NB*NN)          // 32768
#define KNB 16
#define IND 128
#define OUTD 256
#define NEDGE (NTOT*KNB)      // 524288

// ---------------- scratch (device globals; no allocations allowed) ----------
__device__ float d_sqn[NTOT];
__device__ int   d_nbr[NTOT*KNB];
__device__ float d_g1[(size_t)NTOT*OUTD];
__device__ float d_h1[(size_t)NTOT*OUTD];
__device__ float d_g2[(size_t)NTOT*OUTD];
__device__ float d_sc[(size_t)NTOT*OUTD];

// ---------------- squared norms ----------------
__global__ void k_sqn(const float* __restrict__ x) {
    int i = blockIdx.x * blockDim.x + threadIdx.x;
    if (i >= NTOT) return;
    const float4* p = (const float4*)(x + (size_t)i * IND);
    float s = 0.f;
#pragma unroll
    for (int j = 0; j < IND/4; j++) {
        float4 v = p[j];
        s = fmaf(v.x, v.x, s); s = fmaf(v.y, v.y, s);
        s = fmaf(v.z, v.z, s); s = fmaf(v.w, v.w, s);
    }
    d_sqn[i] = s;
}

// ---------------- kNN: per-graph all-pairs + top-16 ----------------
// grid (NN/QT, NB), block 256 (16x16). Each block: QT queries vs all NN cands.
#define QT 64
#define CT 64
#define QPITCH 129

__global__ __launch_bounds__(256) void k_knn(const float* __restrict__ x,
                                             float* __restrict__ esrc,
                                             float* __restrict__ edst,
                                             int write_edges) {
    extern __shared__ float sm[];
    float* qs   = sm;                         // QT*QPITCH
    float* cs   = qs + QT*QPITCH;             // CT*QPITCH
    float* dist = cs + CT*QPITCH;             // QT*(CT+1)
    float* csq  = dist + QT*(CT+1);           // CT

    const int b  = blockIdx.y;
    const int qb = blockIdx.x * QT;           // local (in-graph) query base
    const int t  = threadIdx.x;
    const int tx = t & 15, ty = t >> 4;
    const float* xb = x + (size_t)b * NN * IND;
    const float FINF = __int_as_float(0x7f800000);

    // load query tile [QT x IND]
    for (int idx = t; idx < QT * (IND/4); idx += 256) {
        int r = idx >> 5;                     // IND/4 == 32
        int c4 = (idx & 31) * 4;
        float4 v = *(const float4*)(xb + (size_t)(qb + r) * IND + c4);
        float* dp = qs + r * QPITCH + c4;
        dp[0] = v.x; dp[1] = v.y; dp[2] = v.z; dp[3] = v.w;
    }

    // per-thread top-16 (threads t<QT own query qb+t), sorted ascending by (key, idx)
    float bd[KNB]; int bi[KNB];
#pragma unroll
    for (int k = 0; k < KNB; k++) { bd[k] = FINF; bi[k] = 0; }
    __syncthreads();

    for (int cb = 0; cb < NN; cb += CT) {
        // load candidate tile [CT x IND]
        for (int idx = t; idx < CT * (IND/4); idx += 256) {
            int r = idx >> 5;
            int c4 = (idx & 31) * 4;
            float4 v = *(const float4*)(xb + (size_t)(cb + r) * IND + c4);
            float* dp = cs + r * QPITCH + c4;
            dp[0] = v.x; dp[1] = v.y; dp[2] = v.z; dp[3] = v.w;
        }
        if (t < CT) csq[t] = d_sqn[b * NN + cb + t];
        __syncthreads();

        // 64x64 dots, 4x4 micro-tile per thread
        float acc[4][4];
#pragma unroll
        for (int u = 0; u < 4; u++)
#pragma unroll
            for (int v = 0; v < 4; v++) acc[u][v] = 0.f;

        const float* qp = qs + (ty * 4) * QPITCH;
        const float* cp = cs + (tx * 4) * QPITCH;
#pragma unroll 4
        for (int d = 0; d < IND; d++) {
            float qv[4], cv[4];
#pragma unroll
            for (int u = 0; u < 4; u++) qv[u] = qp[u * QPITCH + d];
#pragma unroll
            for (int v = 0; v < 4; v++) cv[v] = cp[v * QPITCH + d];
#pragma unroll
            for (int u = 0; u < 4; u++)
#pragma unroll
                for (int v = 0; v < 4; v++)
                    acc[u][v] = fmaf(qv[u], cv[v], acc[u][v]);
        }

        // key = sq_j - 2*dot (same ordering as full d2); self -> +inf
#pragma unroll
        for (int u = 0; u < 4; u++) {
            int qi = ty * 4 + u;
#pragma unroll
            for (int v = 0; v < 4; v++) {
                int ci = tx * 4 + v;
                float key = fmaf(-2.f, acc[u][v], csq[ci]);
                if (qb + qi == cb + ci) key = FINF;
                dist[qi * (CT + 1) + ci] = key;
            }
        }
        __syncthreads();

        // selection: thread t<QT merges its row into its sorted-16 list.
        // Scan in increasing index order + strict '<' reproduces top_k tie-break
        // (lower index wins on ties).
        if (t < QT) {
            const float* dr = dist + t * (CT + 1);
            for (int ci = 0; ci < CT; ci++) {
                float key = dr[ci];
                if (key < bd[KNB - 1]) {
                    bd[KNB - 1] = key; bi[KNB - 1] = cb + ci;
#pragma unroll
                    for (int j = KNB - 1; j > 0; j--) {
                        if (bd[j] < bd[j - 1]) {
                            float tf = bd[j]; bd[j] = bd[j - 1]; bd[j - 1] = tf;
                            int   ti = bi[j]; bi[j] = bi[j - 1]; bi[j - 1] = ti;
                        }
                    }
                }
            }
        }
        __syncthreads();
    }

    if (t < QT) {
        int qg = b * NN + qb + t;   // global query id
#pragma unroll
        for (int k = 0; k < KNB; k++) {
            int sg = b * NN + bi[k];            // global neighbor id
            size_t e = (size_t)qg * KNB + k;
            d_nbr[e] = sg;
            if (write_edges) {
                esrc[e] = (float)sg;
                edst[e] = (float)qg;
            }
        }
    }
}

// ---------------- SGEMM 64x64x16, 4x4 micro ----------------
__global__ __launch_bounds__(256) void k_gemm(const float* __restrict__ A,
                                              const float* __restrict__ B,
                                              const float* __restrict__ bias,
                                              float* __restrict__ C,
                                              int M, int Kd, int Nc, int addBias) {
    __shared__ float As[16][65];   // [k][m]
    __shared__ float Bs[16][64];   // [k][n]
    const int t = threadIdx.x;
    const int tx = t & 15, ty = t >> 4;
    const int mb = blockIdx.y * 64, nb = blockIdx.x * 64;

    float acc[4][4];
#pragma unroll
    for (int u = 0; u < 4; u++)
#pragma unroll
        for (int v = 0; v < 4; v++) acc[u][v] = 0.f;

    for (int kb = 0; kb < Kd; kb += 16) {
        {
            int m = t >> 2, kk = (t & 3) * 4;
            float4 v = *(const float4*)(A + (size_t)(mb + m) * Kd + kb + kk);
            As[kk + 0][m] = v.x; As[kk + 1][m] = v.y;
            As[kk + 2][m] = v.z; As[kk + 3][m] = v.w;
        }
        {
            int k = t >> 4, n4 = (t & 15) * 4;
            float4 v = *(const float4*)(B + (size_t)(kb + k) * Nc + nb + n4);
            Bs[k][n4 + 0] = v.x; Bs[k][n4 + 1] = v.y;
            Bs[k][n4 + 2] = v.z; Bs[k][n4 + 3] = v.w;
        }
        __syncthreads();
#pragma unroll
        for (int k = 0; k < 16; k++) {
            float a[4], bv[4];
#pragma unroll
            for (int u = 0; u < 4; u++) a[u] = As[k][ty * 4 + u];
#pragma unroll
            for (int v = 0; v < 4; v++) bv[v] = Bs[k][tx * 4 + v];
#pragma unroll
            for (int u = 0; u < 4; u++)
#pragma unroll
                for (int v = 0; v < 4; v++)
                    acc[u][v] = fmaf(a[u], bv[v], acc[u][v]);
        }
        __syncthreads();
    }
#pragma unroll
    for (int u = 0; u < 4; u++) {
        int m = mb + ty * 4 + u;
#pragma unroll
        for (int v = 0; v < 4; v++) {
            int n = nb + tx * 4 + v;
            float val = acc[u][v];
            if (addBias) val += bias[n];
            C[(size_t)m * Nc + n] = val;
        }
    }
}

// ---------------- GCN aggregation (deg == 17 exactly for all nodes) ---------
// agg = sum_k g[nbr_k]*norm + g[self]*(1/17) + bias  [; relu]
__global__ __launch_bounds__(256) void k_agg_relu(const float* __restrict__ g,
                                                  const float* __restrict__ bias,
                                                  float* __restrict__ out) {
    const int node = blockIdx.x;
    const int t = threadIdx.x;
    __shared__ int nb_s[KNB];
    if (t < KNB) nb_s[t] = d_nbr[(size_t)node * KNB + t];
    __syncthreads();
    const float dinv = rsqrtf(17.0f);
    const float norm = dinv * dinv;
    float acc = 0.f;
#pragma unroll
    for (int k = 0; k < KNB; k++)
        acc += g[(size_t)nb_s[k] * OUTD + t] * norm;
    acc += g[(size_t)node * OUTD + t] * (1.0f / 17.0f);
    acc += bias[t];
    out[(size_t)node * OUTD + t] = fmaxf(acc, 0.f);
}

__global__ __launch_bounds__(256) void k_agg_final(const float* __restrict__ g,
                                                   const float* __restrict__ bias,
                                                   const float* __restrict__ sc,
                                                   float* __restrict__ out) {
    const int node = blockIdx.x;
    const int t = threadIdx.x;
    __shared__ int nb_s[KNB];
    if (t < KNB) nb_s[t] = d_nbr[(size_t)node * KNB + t];
    __syncthreads();
    const float dinv = rsqrtf(17.0f);
    const float norm = dinv * dinv;
    float acc = 0.f;
#pragma unroll
    for (int k = 0; k < KNB; k++)
        acc += g[(size_t)nb_s[k] * OUTD + t] * norm;
    acc += g[(size_t)node * OUTD + t] * (1.0f / 17.0f);
    acc += bias[t];
    acc += sc[(size_t)node * OUTD + t];
    out[(size_t)node * OUTD + t] = acc;
}

// ---------------- launch ----------------
extern "C" void kernel_launch(void* const* d_in, const int* in_sizes, int n_in,
                              void* d_out, int out_size) {
    const float* x  = (const float*)d_in[0];
    // d_in[1] = batch (int32), unused: layout is implied (NB graphs x NN nodes)
    const float* W1 = (const float*)d_in[2];
    const float* b1 = (const float*)d_in[3];
    const float* W2 = (const float*)d_in[4];
    const float* b2 = (const float*)d_in[5];
    const float* Ws = (const float*)d_in[6];
    const float* bs = (const float*)d_in[7];

    float* out  = (float*)d_out;
    float* esrc = out + (size_t)NTOT * OUTD;
    float* edst = esrc + NEDGE;
    int write_edges = (out_size >= (int)((size_t)NTOT * OUTD + 2 * NEDGE)) ? 1 : 0;

    // scratch symbol addresses (pure lookups; capture-safe)
    float *g1, *h1, *g2, *sc;
    cudaGetSymbolAddress((void**)&g1, d_g1);
    cudaGetSymbolAddress((void**)&h1, d_h1);
    cudaGetSymbolAddress((void**)&g2, d_g2);
    cudaGetSymbolAddress((void**)&sc, d_sc);

    const int knn_smem = (QT * QPITCH + CT * QPITCH + QT * (CT + 1) + CT) * (int)sizeof(float);
    cudaFuncSetAttribute(k_knn, cudaFuncAttributeMaxDynamicSharedMemorySize, knn_smem);

    // 1. squared norms
    k_sqn<<<(NTOT + 255) / 256, 256>>>(x);

    // 2. kNN + edge_index output
    k_knn<<<dim3(NN / QT, NB), 256, knn_smem>>>(x, esrc, edst, write_edges);

    // 3. g1 = x @ W1
    k_gemm<<<dim3(OUTD / 64, NTOT / 64), 256>>>(x, W1, b1, g1, NTOT, IND, OUTD, 0);

    // 4. h1 = relu(agg(g1) + b1)
    k_agg_relu<<<NTOT, 256>>>(g1, b1, h1);

    // 5. g2 = h1 @ W2
    k_gemm<<<dim3(OUTD / 64, NTOT / 64), 256>>>(h1, W2, b2, g2, NTOT, OUTD, OUTD, 0);

    // 6. sc = x @ Ws + bs
    k_gemm<<<dim3(OUTD / 64, NTOT / 64), 256>>>(x, Ws, bs, sc, NTOT, IND, OUTD, 1);

    // 7. out = agg(g2) + b2 + sc
    k_agg_final<<<NTOT, 256>>>(g2, b2, sc, out);
}

// round 2
// speedup vs baseline: 1.3434x; 1.3434x over previous
#include <cuda_runtime.h>
#include <math.h>
#include <stdint.h>

#define NB 16
#define NN 2048
#define NTOT (NB*NN)          // 32768
#define KNB 16
#define IND 128
#define OUTD 256
#define NEDGE (NTOT*KNB)      // 524288

// ---------------- scratch (device globals; no allocations allowed) ----------
__device__ float d_sqn[NTOT];
__device__ int   d_nbr[NTOT*KNB];
__device__ float d_g1[(size_t)NTOT*OUTD];
__device__ float d_h1[(size_t)NTOT*OUTD];
__device__ float d_g2[(size_t)NTOT*OUTD];
__device__ float d_sc[(size_t)NTOT*OUTD];

// ---------------- f32x2 helpers ----------------
__device__ __forceinline__ unsigned long long pack_dup(float v) {
    unsigned long long r;
    asm("mov.b64 %0, {%1, %1};" : "=l"(r) : "f"(v));
    return r;
}
__device__ __forceinline__ unsigned long long fma2(unsigned long long a,
                                                   unsigned long long b,
                                                   unsigned long long c) {
    unsigned long long d;
    asm("fma.rn.f32x2 %0, %1, %2, %3;" : "=l"(d) : "l"(a), "l"(b), "l"(c));
    return d;
}
__device__ __forceinline__ void unpack2(unsigned long long v, float& lo, float& hi) {
    asm("mov.b64 {%0, %1}, %2;" : "=f"(lo), "=f"(hi) : "l"(v));
}

// ---------------- squared norms ----------------
__global__ void k_sqn(const float* __restrict__ x) {
    int i = blockIdx.x * blockDim.x + threadIdx.x;
    if (i >= NTOT) return;
    const float4* p = (const float4*)(x + (size_t)i * IND);
    float s = 0.f;
#pragma unroll
    for (int j = 0; j < IND/4; j++) {
        float4 v = p[j];
        s = fmaf(v.x, v.x, s); s = fmaf(v.y, v.y, s);
        s = fmaf(v.z, v.z, s); s = fmaf(v.w, v.w, s);
    }
    d_sqn[i] = s;
}

// ---------------- kNN: per-graph all-pairs + top-16 (f32x2 compute) --------
// grid (NN/128, NB), block 256. Tile: 128 queries x 128 candidates resident.
#define QT 128
#define CT 128
#define QP 132          // smem pitch for [d][node] tiles
#define DP 130          // dist pitch (even -> 8B-aligned pair stores)

__global__ __launch_bounds__(256) void k_knn(const float* __restrict__ x,
                                             float* __restrict__ esrc,
                                             float* __restrict__ edst,
                                             int write_edges) {
    extern __shared__ float sm[];
    float* qs   = sm;                  // [IND][QP]  (transposed: [d][q])
    float* cs   = qs + IND*QP;         // [IND][QP]  ([d][c])
    float* dist = cs + IND*QP;         // [QT][DP]
    float* csq  = dist + QT*DP;        // [CT]

    const int b  = blockIdx.y;
    const int qb = blockIdx.x * QT;
    const int t  = threadIdx.x;
    const int tx = t & 15, ty = t >> 4;
    const float* xb = x + (size_t)b * NN * IND;
    const float FINF = __int_as_float(0x7f800000);

    // load query tile transposed [d][q]
    for (int idx = t; idx < QT * (IND/4); idx += 256) {
        int q = idx & (QT - 1);
        int dc = idx >> 7;                       // 0..31
        float4 v = *(const float4*)(xb + (size_t)(qb + q) * IND + dc * 4);
        qs[(dc*4 + 0)*QP + q] = v.x;
        qs[(dc*4 + 1)*QP + q] = v.y;
        qs[(dc*4 + 2)*QP + q] = v.z;
        qs[(dc*4 + 3)*QP + q] = v.w;
    }

    // selection state: 2 threads per query (halves of candidate tile)
    const int myq   = t >> 1;          // 0..127
    const int myh   = t & 1;           // half
    float bd[KNB]; int bi[KNB];
#pragma unroll
    for (int k = 0; k < KNB; k++) { bd[k] = FINF; bi[k] = 0; }

    for (int cb = 0; cb < NN; cb += CT) {
        // load candidate tile transposed [d][c]
        for (int idx = t; idx < CT * (IND/4); idx += 256) {
            int c = idx & (CT - 1);
            int dc = idx >> 7;
            float4 v = *(const float4*)(xb + (size_t)(cb + c) * IND + dc * 4);
            cs[(dc*4 + 0)*QP + c] = v.x;
            cs[(dc*4 + 1)*QP + c] = v.y;
            cs[(dc*4 + 2)*QP + c] = v.z;
            cs[(dc*4 + 3)*QP + c] = v.w;
        }
        if (t < CT) csq[t] = d_sqn[b * NN + cb + t];
        __syncthreads();

        // 128x128 dots; per-thread 8q x 8c split into 2x 4-wide groups.
        // queries: ty*4+u (u<4), 64+ty*4+(u-4); cands: tx*4+(0..3), 64+tx*4+(0..3)
        unsigned long long acc[8][4];
#pragma unroll
        for (int u = 0; u < 8; u++)
#pragma unroll
            for (int v = 0; v < 4; v++) acc[u][v] = 0ULL;

#pragma unroll 8
        for (int d = 0; d < IND; d++) {
            const float* qr = qs + d * QP + ty * 4;
            const float* cr = cs + d * QP + tx * 4;
            float4 q0 = *(const float4*)qr;
            float4 q1 = *(const float4*)(qr + 64);
            unsigned long long c0 = *(const unsigned long long*)cr;
            unsigned long long c1 = *(const unsigned long long*)(cr + 2);
            unsigned long long c2 = *(const unsigned long long*)(cr + 64);
            unsigned long long c3 = *(const unsigned long long*)(cr + 66);
            unsigned long long qq[8];
            qq[0] = pack_dup(q0.x); qq[1] = pack_dup(q0.y);
            qq[2] = pack_dup(q0.z); qq[3] = pack_dup(q0.w);
            qq[4] = pack_dup(q1.x); qq[5] = pack_dup(q1.y);
            qq[6] = pack_dup(q1.z); qq[7] = pack_dup(q1.w);
#pragma unroll
            for (int u = 0; u < 8; u++) {
                acc[u][0] = fma2(qq[u], c0, acc[u][0]);
                acc[u][1] = fma2(qq[u], c1, acc[u][1]);
                acc[u][2] = fma2(qq[u], c2, acc[u][2]);
                acc[u][3] = fma2(qq[u], c3, acc[u][3]);
            }
        }

        // keys into dist: key = csq[c] - 2*dot; self -> +inf
#pragma unroll
        for (int u = 0; u < 8; u++) {
            int ql = (u < 4) ? (ty*4 + u) : (64 + ty*4 + u - 4);
#pragma unroll
            for (int v = 0; v < 4; v++) {
                int c0i = (v < 2) ? (tx*4 + 2*v) : (64 + tx*4 + 2*(v - 2));
                float dlo, dhi;
                unpack2(acc[u][v], dlo, dhi);
                float k0 = fmaf(-2.f, dlo, csq[c0i]);
                float k1 = fmaf(-2.f, dhi, csq[c0i + 1]);
                if (qb + ql == cb + c0i)     k0 = FINF;
                if (qb + ql == cb + c0i + 1) k1 = FINF;
                float2 kv = make_float2(k0, k1);
                *(float2*)(dist + ql * DP + c0i) = kv;
            }
        }
        __syncthreads();

        // selection: thread scans its 64-cand half, ascending index order.
        {
            const float* dr = dist + myq * DP + myh * 64;
            const int ibase = cb + myh * 64;
#pragma unroll 4
            for (int ci = 0; ci < 64; ci++) {
                float key = dr[ci];
                if (key < bd[KNB - 1]) {
                    bd[KNB - 1] = key; bi[KNB - 1] = ibase + ci;
#pragma unroll
                    for (int j = KNB - 1; j > 0; j--) {
                        if (bd[j] < bd[j - 1]) {
                            float tf = bd[j]; bd[j] = bd[j - 1]; bd[j - 1] = tf;
                            int   ti = bi[j]; bi[j] = bi[j - 1]; bi[j - 1] = ti;
                        }
                    }
                }
            }
        }
        __syncthreads();
    }

    // dump both half-lists to smem (reuse dist): keys at [q][h*16+j], idx at [q][32+h*16+j]
#pragma unroll
    for (int j = 0; j < KNB; j++) {
        dist[myq * DP + myh * KNB + j] = bd[j];
        dist[myq * DP + 32 + myh * KNB + j] = __int_as_float(bi[j]);
    }
    __syncthreads();

    // one thread per query merges the two sorted lists (tie: lower idx first)
    if (t < QT) {
        const float* ka = dist + t * DP;
        const float* kb_ = ka + KNB;
        const float* ia = ka + 32;
        const float* ib = ka + 48;
        int pa = 0, pb = 0;
        int qg = b * NN + qb + t;
#pragma unroll
        for (int k = 0; k < KNB; k++) {
            float kva = ka[pa], kvb = kb_[pb];
            int   iva = __float_as_int(ia[pa]), ivb = __float_as_int(ib[pb]);
            bool takeA = (kva < kvb) || (kva == kvb && iva < ivb);
            int sel = takeA ? iva : ivb;
            if (takeA) pa++; else pb++;
            int sg = b * NN + sel;
            size_t e = (size_t)qg * KNB + k;
            d_nbr[e] = sg;
            if (write_edges) {
                esrc[e] = (float)sg;
                edst[e] = (float)qg;
            }
        }
    }
}

// ---------------- SGEMM 128x128, f32x2 micro, K chunk 32 ----------------
#define GKC 32
__global__ __launch_bounds__(256) void k_gemm(const float* __restrict__ A,
                                              const float* __restrict__ B,
                                              const float* __restrict__ bias,
                                              float* __restrict__ C,
                                              int Kd, int Nc, int addBias) {
    __shared__ float As[GKC][QP];   // [k][m]
    __shared__ float Bs[GKC][QP];   // [k][n]
    const int t = threadIdx.x;
    const int tx = t & 15, ty = t >> 4;
    const int nb = blockIdx.x * 128, mb = blockIdx.y * 128;

    unsigned long long acc[8][4];
#pragma unroll
    for (int u = 0; u < 8; u++)
#pragma unroll
        for (int v = 0; v < 4; v++) acc[u][v] = 0ULL;

    for (int kb = 0; kb < Kd; kb += GKC) {
        // A chunk transposed: 128 rows x 32 cols
        for (int idx = t; idx < 128 * (GKC/4); idx += 256) {
            int m = idx & 127, kc = idx >> 7;    // kc 0..7
            float4 v = *(const float4*)(A + (size_t)(mb + m) * Kd + kb + kc * 4);
            As[kc*4 + 0][m] = v.x; As[kc*4 + 1][m] = v.y;
            As[kc*4 + 2][m] = v.z; As[kc*4 + 3][m] = v.w;
        }
        // B chunk natural [k][n]
        for (int idx = t; idx < GKC * (128/4); idx += 256) {
            int n4 = idx & 31, k = idx >> 5;
            float4 v = *(const float4*)(B + (size_t)(kb + k) * Nc + nb + n4 * 4);
            *(float4*)(&Bs[k][n4 * 4]) = v;
        }
        __syncthreads();

#pragma unroll
        for (int k = 0; k < GKC; k++) {
            const float* ar = &As[k][ty * 4];
            const float* br = &Bs[k][tx * 4];
            float4 a0 = *(const float4*)ar;
            float4 a1 = *(const float4*)(ar + 64);
            unsigned long long b0 = *(const unsigned long long*)br;
            unsigned long long b1 = *(const unsigned long long*)(br + 2);
            unsigned long long b2 = *(const unsigned long long*)(br + 64);
            unsigned long long b3 = *(const unsigned long long*)(br + 66);
            unsigned long long aa[8];
            aa[0] = pack_dup(a0.x); aa[1] = pack_dup(a0.y);
            aa[2] = pack_dup(a0.z); aa[3] = pack_dup(a0.w);
            aa[4] = pack_dup(a1.x); aa[5] = pack_dup(a1.y);
            aa[6] = pack_dup(a1.z); aa[7] = pack_dup(a1.w);
#pragma unroll
            for (int u = 0; u < 8; u++) {
                acc[u][0] = fma2(aa[u], b0, acc[u][0]);
                acc[u][1] = fma2(aa[u], b1, acc[u][1]);
                acc[u][2] = fma2(aa[u], b2, acc[u][2]);
                acc[u][3] = fma2(aa[u], b3, acc[u][3]);
            }
        }
        __syncthreads();
    }

#pragma unroll
    for (int u = 0; u < 8; u++) {
        int m = mb + ((u < 4) ? (ty*4 + u) : (64 + ty*4 + u - 4));
#pragma unroll
        for (int g = 0; g < 2; g++) {
            int n = nb + ((g == 0) ? (tx*4) : (64 + tx*4));
            float4 o;
            unpack2(acc[u][g*2 + 0], o.x, o.y);
            unpack2(acc[u][g*2 + 1], o.z, o.w);
            if (addBias) {
                o.x += bias[n + 0]; o.y += bias[n + 1];
                o.z += bias[n + 2]; o.w += bias[n + 3];
            }
            *(float4*)(C + (size_t)m * Nc + n) = o;
        }
    }
}

// ---------------- GCN aggregation (deg == 17 exactly for all nodes) ---------
__global__ __launch_bounds__(256) void k_agg_relu(const float* __restrict__ g,
                                                  const float* __restrict__ bias,
                                                  float* __restrict__ out) {
    const int node = blockIdx.x;
    const int t = threadIdx.x;
    __shared__ int nb_s[KNB];
    if (t < KNB) nb_s[t] = d_nbr[(size_t)node * KNB + t];
    __syncthreads();
    const float dinv = rsqrtf(17.0f);
    const float norm = dinv * dinv;
    float acc = 0.f;
#pragma unroll
    for (int k = 0; k < KNB; k++)
        acc += g[(size_t)nb_s[k] * OUTD + t] * norm;
    acc += g[(size_t)node * OUTD + t] * (1.0f / 17.0f);
    acc += bias[t];
    out[(size_t)node * OUTD + t] = fmaxf(acc, 0.f);
}

__global__ __launch_bounds__(256) void k_agg_final(const float* __restrict__ g,
                                                   const float* __restrict__ bias,
                                                   const float* __restrict__ sc,
                                                   float* __restrict__ out) {
    const int node = blockIdx.x;
    const int t = threadIdx.x;
    __shared__ int nb_s[KNB];
    if (t < KNB) nb_s[t] = d_nbr[(size_t)node * KNB + t];
    __syncthreads();
    const float dinv = rsqrtf(17.0f);
    const float norm = dinv * dinv;
    float acc = 0.f;
#pragma unroll
    for (int k = 0; k < KNB; k++)
        acc += g[(size_t)nb_s[k] * OUTD + t] * norm;
    acc += g[(size_t)node * OUTD + t] * (1.0f / 17.0f);
    acc += bias[t];
    acc += sc[(size_t)node * OUTD + t];
    out[(size_t)node * OUTD + t] = acc;
}

// ---------------- launch ----------------
extern "C" void kernel_launch(void* const* d_in, const int* in_sizes, int n_in,
                              void* d_out, int out_size) {
    const float* x  = (const float*)d_in[0];
    const float* W1 = (const float*)d_in[2];
    const float* b1 = (const float*)d_in[3];
    const float* W2 = (const float*)d_in[4];
    const float* b2 = (const float*)d_in[5];
    const float* Ws = (const float*)d_in[6];
    const float* bs = (const float*)d_in[7];

    float* out  = (float*)d_out;
    float* esrc = out + (size_t)NTOT * OUTD;
    float* edst = esrc + NEDGE;
    int write_edges = (out_size >= (int)((size_t)NTOT * OUTD + 2 * NEDGE)) ? 1 : 0;

    float *g1, *h1, *g2, *sc;
    cudaGetSymbolAddress((void**)&g1, d_g1);
    cudaGetSymbolAddress((void**)&h1, d_h1);
    cudaGetSymbolAddress((void**)&g2, d_g2);
    cudaGetSymbolAddress((void**)&sc, d_sc);

    const int knn_smem = (IND*QP + IND*QP + QT*DP + CT) * (int)sizeof(float);
    static int attr_set = 0;
    cudaFuncSetAttribute(k_knn, cudaFuncAttributeMaxDynamicSharedMemorySize, knn_smem);
    (void)attr_set;

    // 1. squared norms
    k_sqn<<<(NTOT + 255) / 256, 256>>>(x);

    // 2. kNN + edge_index output
    k_knn<<<dim3(NN / QT, NB), 256, knn_smem>>>(x, esrc, edst, write_edges);

    // 3. g1 = x @ W1
    k_gemm<<<dim3(OUTD / 128, NTOT / 128), 256>>>(x, W1, b1, g1, IND, OUTD, 0);

    // 4. h1 = relu(agg(g1) + b1)
    k_agg_relu<<<NTOT, 256>>>(g1, b1, h1);

    // 5. g2 = h1 @ W2
    k_gemm<<<dim3(OUTD / 128, NTOT / 128), 256>>>(h1, W2, b2, g2, OUTD, OUTD, 0);

    // 6. sc = x @ Ws + bs
    k_gemm<<<dim3(OUTD / 128, NTOT / 128), 256>>>(x, Ws, bs, sc, IND, OUTD, 1);

    // 7. out = agg(g2) + b2 + sc
    k_agg_final<<<NTOT, 256>>>(g2, b2, sc, out);
}